// round 2
// baseline (speedup 1.0000x reference)
#include <cuda_runtime.h>

#define Bsz 4096
#define Hdim 1024
#define Kmix 10
#define Lw 64
#define Vv 80
#define N3K 30
#define TNp 32   // padded N

// Intermediate: raw linear outputs, padded stride 32 (cols 30,31 unused)
__device__ float g_out30[Bsz * TNp];

// ---------------------------------------------------------------------------
// Kernel 1: out30 = x @ W    (bias added later, inside the exp)
// M=4096, N=30(->32), K=1024. TM=32 rows/block, 128 blocks, 256 threads.
// 2x2 register blocking: per h-step 3 LDS + 4 FFMA -> FMA-pipe bound.
// ---------------------------------------------------------------------------
__global__ __launch_bounds__(256) void gemm_kernel(const float* __restrict__ x,
                                                   const float* __restrict__ W) {
    const int TM = 32, HC = 64;
    __shared__ float xs[TM][68];   // pad 68: rows differ by 4 banks -> no conflicts
    __shared__ float ws[HC][TNp];

    const int tid = threadIdx.x;
    const int tx  = tid & 15;      // col group: cols 2*tx, 2*tx+1
    const int ty  = tid >> 4;      // row group: rows 2*ty, 2*ty+1
    const int row0 = blockIdx.x * TM;

    float a00 = 0.f, a01 = 0.f, a10 = 0.f, a11 = 0.f;

    for (int h0 = 0; h0 < Hdim; h0 += HC) {
        // load x tile: 32 rows x 64 cols, float4 vectorized
        #pragma unroll
        for (int i = 0; i < 2; ++i) {
            int idx = tid + i * 256;          // 0..511
            int r = idx >> 4, hq = idx & 15;
            float4 v = *(const float4*)&x[(size_t)(row0 + r) * Hdim + h0 + hq * 4];
            *(float4*)&xs[r][hq * 4] = v;
        }
        // load W tile: 64 x 30 -> padded 64 x 32
        #pragma unroll
        for (int i = 0; i < 8; ++i) {
            int idx = tid + i * 256;          // 0..2047
            int h = idx >> 5, k = idx & 31;
            ws[h][k] = (k < N3K) ? W[(size_t)(h0 + h) * N3K + k] : 0.f;
        }
        __syncthreads();

        const int r0 = ty * 2, c0 = tx * 2;
        #pragma unroll 8
        for (int h = 0; h < HC; ++h) {
            float x0 = xs[r0][h];
            float x1 = xs[r0 + 1][h];
            float2 w = *(const float2*)&ws[h][c0];
            a00 += x0 * w.x;  a01 += x0 * w.y;
            a10 += x1 * w.x;  a11 += x1 * w.y;
        }
        __syncthreads();
    }

    const int gr = row0 + ty * 2, c = tx * 2;
    *(float2*)&g_out30[(size_t)gr * TNp + c]       = make_float2(a00, a01);
    *(float2*)&g_out30[(size_t)(gr + 1) * TNp + c] = make_float2(a10, a11);
}

// ---------------------------------------------------------------------------
// Kernel 2: per batch row -- exp params, phi over L=64, window = phi @ chars.
// 4096 blocks x 160 threads. chars loads (float4) are prefetched BEFORE the
// phi computation so HBM traffic overlaps the MUFU/ALU work.
// thread -> (v4 = tid%20, lgroup = tid/20), each lgroup covers 8 L-slots.
// ---------------------------------------------------------------------------
__global__ __launch_bounds__(160) void window_kernel(const float* __restrict__ chars,
                                                     const float* __restrict__ bias,
                                                     float* __restrict__ out) {
    __shared__ float  se[32];          // exp(alpha_raw), exp(beta_raw), exp(kappa_raw)
    __shared__ float  phi[Lw];
    __shared__ float4 part[8][20];

    const int b   = blockIdx.x;
    const int tid = threadIdx.x;
    const int v4  = tid % 20;
    const int g   = tid / 20;

    // Prefetch this thread's 8 char float4s (independent of phi)
    const float4* ch = (const float4*)(chars + (size_t)b * Lw * Vv);
    float4 c[8];
    #pragma unroll
    for (int i = 0; i < 8; ++i)
        c[i] = ch[(g * 8 + i) * (Vv / 4) + v4];

    // exp of the 30 raw params (+ bias)
    if (tid < N3K)
        se[tid] = expf(g_out30[(size_t)b * TNp + tid] + bias[tid]);
    __syncthreads();

    // phi[l] = sum_k alpha_k * exp(-beta_k * (kappa_k - l)^2)
    if (tid < Lw) {
        float u = (float)tid;
        float s = 0.f;
        #pragma unroll
        for (int k = 0; k < Kmix; ++k) {
            float d = se[20 + k] - u;
            s += se[k] * expf(-se[10 + k] * d * d);
        }
        phi[tid] = s;
    }
    __syncthreads();

    // window accumulation over this thread's 8 L-slots
    float4 acc = make_float4(0.f, 0.f, 0.f, 0.f);
    #pragma unroll
    for (int i = 0; i < 8; ++i) {
        float p = phi[g * 8 + i];
        acc.x += p * c[i].x;  acc.y += p * c[i].y;
        acc.z += p * c[i].z;  acc.w += p * c[i].w;
    }
    part[g][v4] = acc;
    __syncthreads();

    // reduce the 8 lgroup partials, vectorized store
    if (tid < 20) {
        float4 s = part[0][tid];
        #pragma unroll
        for (int g2 = 1; g2 < 8; ++g2) {
            float4 p = part[g2][tid];
            s.x += p.x;  s.y += p.y;  s.z += p.z;  s.w += p.w;
        }
        ((float4*)out)[(size_t)b * (Vv / 4) + tid] = s;
    }
}

// ---------------------------------------------------------------------------
extern "C" void kernel_launch(void* const* d_in, const int* in_sizes, int n_in,
                              void* d_out, int out_size) {
    const float* x     = (const float*)d_in[0];   // [4096, 1024]
    const float* chars = (const float*)d_in[1];   // [4096, 64, 80]
    const float* W     = (const float*)d_in[2];   // [1024, 30]
    const float* bvec  = (const float*)d_in[3];   // [30]
    float*       out   = (float*)d_out;           // [4096, 80]

    gemm_kernel<<<Bsz / 32, 256>>>(x, W);
    window_kernel<<<Bsz, 160>>>(chars, bvec, out);
}

// round 6
// speedup vs baseline: 1.2243x; 1.2243x over previous
#include <cuda_runtime.h>

#define Bsz 4096
#define Hdim 1024
#define Kmix 10
#define Lw 64
#define Vv 80
#define N3K 30
#define Rrows 8
#define NBLK (Bsz / Rrows)   // 512 blocks
#define NTHR 256

// ---------------------------------------------------------------------------
// One fused kernel: per block, 8 batch rows.
//  Phase 1 (GEMM): thread (k=lane, slice=warp) accumulates out[r][k] over
//     h in [warp*128, warp*128+128). x read as broadcast float4 LDG (L1-hit),
//     W read coalesced (L2-resident, 122KB). No smem/barriers in inner loop.
//  Phase 2: cross-warp reduce in smem, + bias, exp -> se[r][30]
//  Phase 3: phi[r][l] = sum_k alpha*exp(-beta*(kappa-l)^2)
//  Phase 4 (window): warp w <-> row w, lanes 0..19 own one float4 v-column,
//     stream chars (DRAM-bound part), unrolled for MLP.
// ---------------------------------------------------------------------------
__global__ __launch_bounds__(NTHR, 2) void fused_kernel(
    const float* __restrict__ x, const float* __restrict__ chars,
    const float* __restrict__ W, const float* __restrict__ bias,
    float* __restrict__ out)
{
    __shared__ float part[8][Rrows][32];   // 8KB: per-slice GEMM partials
    __shared__ float se[Rrows][32];        // exp(alpha|beta|kappa) per row
    __shared__ float phi_s[Rrows][Lw];     // 2KB

    const int tid  = threadIdx.x;
    const int lane = tid & 31;
    const int w    = tid >> 5;             // warp id: h-slice, later row id
    const int b0   = blockIdx.x * Rrows;

    // ---------------- Phase 1: GEMM partials --------------------------------
    float acc[Rrows];
    #pragma unroll
    for (int r = 0; r < Rrows; ++r) acc[r] = 0.f;

    const int  h0     = w * 128;
    const bool kvalid = (lane < N3K);

    #pragma unroll 2
    for (int hh = 0; hh < 128; hh += 4) {
        const int h = h0 + hh;
        float4 xv[Rrows];
        #pragma unroll
        for (int r = 0; r < Rrows; ++r)
            xv[r] = *(const float4*)&x[(size_t)(b0 + r) * Hdim + h];
        float w0 = kvalid ? W[(size_t)(h + 0) * N3K + lane] : 0.f;
        float w1 = kvalid ? W[(size_t)(h + 1) * N3K + lane] : 0.f;
        float w2 = kvalid ? W[(size_t)(h + 2) * N3K + lane] : 0.f;
        float w3 = kvalid ? W[(size_t)(h + 3) * N3K + lane] : 0.f;
        #pragma unroll
        for (int r = 0; r < Rrows; ++r) {
            acc[r] += xv[r].x * w0;
            acc[r] += xv[r].y * w1;
            acc[r] += xv[r].z * w2;
            acc[r] += xv[r].w * w3;
        }
    }
    #pragma unroll
    for (int r = 0; r < Rrows; ++r) part[w][r][lane] = acc[r];
    __syncthreads();

    // ---------------- Phase 2: reduce + bias + exp --------------------------
    if (tid < Rrows * N3K) {
        const int r = tid / N3K, k = tid - r * N3K;
        float s = 0.f;
        #pragma unroll
        for (int ww = 0; ww < 8; ++ww) s += part[ww][r][k];
        se[r][k] = expf(s + bias[k]);
    }
    __syncthreads();

    // ---------------- Phase 3: phi ------------------------------------------
    #pragma unroll
    for (int i = 0; i < 2; ++i) {
        const int idx = tid + i * NTHR;        // 512 = 8 rows x 64 L
        const int r = idx >> 6, l = idx & 63;
        const float u = (float)l;
        float s = 0.f;
        #pragma unroll
        for (int k = 0; k < Kmix; ++k) {
            float d = se[r][20 + k] - u;
            s += se[r][k] * expf(-se[r][10 + k] * d * d);
        }
        phi_s[r][l] = s;
    }
    __syncthreads();

    // ---------------- Phase 4: window (DRAM-bound streaming) ----------------
    if (lane < Vv / 4) {                       // 20 float4 columns
        const float4* ch4 = (const float4*)(chars + (size_t)(b0 + w) * Lw * Vv);
        float4 a = make_float4(0.f, 0.f, 0.f, 0.f);
        #pragma unroll 8
        for (int l = 0; l < Lw; ++l) {
            const float  p = phi_s[w][l];
            const float4 c = ch4[l * (Vv / 4) + lane];
            a.x += p * c.x;  a.y += p * c.y;
            a.z += p * c.z;  a.w += p * c.w;
        }
        ((float4*)out)[(size_t)(b0 + w) * (Vv / 4) + lane] = a;
    }
}

// ---------------------------------------------------------------------------
extern "C" void kernel_launch(void* const* d_in, const int* in_sizes, int n_in,
                              void* d_out, int out_size) {
    const float* x     = (const float*)d_in[0];   // [4096, 1024]
    const float* chars = (const float*)d_in[1];   // [4096, 64, 80]
    const float* W     = (const float*)d_in[2];   // [1024, 30]
    const float* bvec  = (const float*)d_in[3];   // [30]
    float*       out   = (float*)d_out;           // [4096, 80]

    fused_kernel<<<NBLK, NTHR>>>(x, chars, W, bvec, out);
}

// round 8
// speedup vs baseline: 1.3237x; 1.0811x over previous
#include <cuda_runtime.h>

#define Bsz 4096
#define Hdim 1024
#define Kmix 10
#define Lw 64
#define Vv 80
#define N3K 30
#define Rrows 8
#define NBLK (Bsz / Rrows)   // 512 blocks
#define NTHR 256

// phi[b][l], written by kernel A, streamed by kernel B (1 MB)
__device__ float g_phi[Bsz * Lw];

// ---------------------------------------------------------------------------
// Kernel A: x@W + b -> exp -> mixture -> phi.  512 blocks x 256 threads,
// 8 batch rows per block. Warp w owns h-slice [w*128, w*128+128);
// lane = output column k (0..29). Broadcast float4 x loads (L1-hit after
// first warp), coalesced W loads (L1/L2-resident slice). 32 FFMA : 12 LDG
// per 4-h step -> FMA-issue bound, no inner-loop barriers.
// ---------------------------------------------------------------------------
__global__ __launch_bounds__(NTHR, 2) void gemm_phi_kernel(
    const float* __restrict__ x, const float* __restrict__ W,
    const float* __restrict__ bias)
{
    __shared__ float part[8][Rrows][32];   // per-slice GEMM partials
    __shared__ float se[Rrows][32];        // exp(alpha|beta|kappa)

    const int tid  = threadIdx.x;
    const int lane = tid & 31;
    const int w    = tid >> 5;
    const int b0   = blockIdx.x * Rrows;

    // ---- Phase 1: GEMM partials -------------------------------------------
    float acc[Rrows];
    #pragma unroll
    for (int r = 0; r < Rrows; ++r) acc[r] = 0.f;

    const int  h0     = w * 128;
    const bool kvalid = (lane < N3K);

    #pragma unroll 2
    for (int hh = 0; hh < 128; hh += 4) {
        const int h = h0 + hh;
        float4 xv[Rrows];
        #pragma unroll
        for (int r = 0; r < Rrows; ++r)
            xv[r] = *(const float4*)&x[(size_t)(b0 + r) * Hdim + h];
        float w0 = kvalid ? W[(size_t)(h + 0) * N3K + lane] : 0.f;
        float w1 = kvalid ? W[(size_t)(h + 1) * N3K + lane] : 0.f;
        float w2 = kvalid ? W[(size_t)(h + 2) * N3K + lane] : 0.f;
        float w3 = kvalid ? W[(size_t)(h + 3) * N3K + lane] : 0.f;
        #pragma unroll
        for (int r = 0; r < Rrows; ++r) {
            acc[r] += xv[r].x * w0;
            acc[r] += xv[r].y * w1;
            acc[r] += xv[r].z * w2;
            acc[r] += xv[r].w * w3;
        }
    }
    #pragma unroll
    for (int r = 0; r < Rrows; ++r) part[w][r][lane] = acc[r];
    __syncthreads();

    // ---- Phase 2: reduce + bias + exp -------------------------------------
    if (tid < Rrows * N3K) {
        const int r = tid / N3K, k = tid - r * N3K;
        float s = 0.f;
        #pragma unroll
        for (int ww = 0; ww < 8; ++ww) s += part[ww][r][k];
        se[r][k] = expf(s + bias[k]);
    }
    __syncthreads();

    // ---- Phase 3: phi -> global -------------------------------------------
    #pragma unroll
    for (int i = 0; i < 2; ++i) {
        const int idx = tid + i * NTHR;        // 512 = 8 rows x 64 L
        const int r = idx >> 6, l = idx & 63;
        const float u = (float)l;
        float s = 0.f;
        #pragma unroll
        for (int k = 0; k < Kmix; ++k) {
            float d = se[r][20 + k] - u;
            s += se[r][k] * expf(-se[r][10 + k] * d * d);
        }
        g_phi[(size_t)(b0 + r) * Lw + l] = s;
    }
}

// ---------------------------------------------------------------------------
// Kernel B: out[b] = phi[b] @ chars[b].  4096 blocks x 160 threads,
// thread -> (v4 = tid%20 float4-column, g = tid/20 covering 8 L-slots).
// 8 float4 char loads prefetched up front -> high MLP, DRAM-bound.
// ---------------------------------------------------------------------------
__global__ __launch_bounds__(160) void window_kernel(const float* __restrict__ chars,
                                                     float* __restrict__ out) {
    __shared__ float  phi_s[Lw];
    __shared__ float4 part[8][20];

    const int b   = blockIdx.x;
    const int tid = threadIdx.x;
    const int v4  = tid % 20;
    const int g   = tid / 20;

    // Prefetch this thread's 8 char float4s
    const float4* ch = (const float4*)(chars + (size_t)b * Lw * Vv);
    float4 c[8];
    #pragma unroll
    for (int i = 0; i < 8; ++i)
        c[i] = ch[(g * 8 + i) * (Vv / 4) + v4];

    if (tid < Lw)
        phi_s[tid] = g_phi[(size_t)b * Lw + tid];
    __syncthreads();

    float4 acc = make_float4(0.f, 0.f, 0.f, 0.f);
    #pragma unroll
    for (int i = 0; i < 8; ++i) {
        float p = phi_s[g * 8 + i];
        acc.x += p * c[i].x;  acc.y += p * c[i].y;
        acc.z += p * c[i].z;  acc.w += p * c[i].w;
    }
    part[g][v4] = acc;
    __syncthreads();

    if (tid < 20) {
        float4 s = part[0][tid];
        #pragma unroll
        for (int g2 = 1; g2 < 8; ++g2) {
            float4 p = part[g2][tid];
            s.x += p.x;  s.y += p.y;  s.z += p.z;  s.w += p.w;
        }
        ((float4*)out)[(size_t)b * (Vv / 4) + tid] = s;
    }
}

// ---------------------------------------------------------------------------
extern "C" void kernel_launch(void* const* d_in, const int* in_sizes, int n_in,
                              void* d_out, int out_size) {
    const float* x     = (const float*)d_in[0];   // [4096, 1024]
    const float* chars = (const float*)d_in[1];   // [4096, 64, 80]
    const float* W     = (const float*)d_in[2];   // [1024, 30]
    const float* bvec  = (const float*)d_in[3];   // [30]
    float*       out   = (float*)d_out;           // [4096, 80]

    gemm_phi_kernel<<<NBLK, NTHR>>>(x, W, bvec);
    window_kernel<<<Bsz, 160>>>(chars, out);
}

// round 9
// speedup vs baseline: 1.4117x; 1.0665x over previous
#include <cuda_runtime.h>

#define Bsz 4096
#define Hdim 1024
#define Kmix 10
#define Lw 64
#define Vv 80
#define N3K 30
#define Rrows 8
#define NBLK (Bsz / Rrows)   // 512 blocks
#define NTHR 256

typedef unsigned long long ull;

// phi[b][l], written by kernel A, streamed by kernel B (1 MB)
__device__ float g_phi[Bsz * Lw];

// packed dual-FMA: d = a*b + c elementwise on {lo,hi} fp32 pairs
#define FFMA2(d, a, b, c) \
    asm("fma.rn.f32x2 %0, %1, %2, %3;" : "=l"(d) : "l"(a), "l"(b), "l"(c))

// ---------------------------------------------------------------------------
// Kernel A: x@W + b -> exp -> mixture -> phi.
// 512 blocks x 256 threads, 8 batch rows/block.
//   Stage:   coalesced float4 staging of x rows into smem (32KB).
//   Phase 1: warp w owns h-slice [w*128,(w+1)*128), lane = k.
//            ulonglong2 LDS.128 of staged x gives packed {x[h],x[h+1]} pairs;
//            fma.rn.f32x2 accumulates even/odd h in one 64-bit register.
//   Phase 2: cross-warp reduce + bias + exp.   Phase 3: phi -> global.
// ---------------------------------------------------------------------------
__global__ __launch_bounds__(NTHR, 4) void gemm_phi_kernel(
    const float* __restrict__ x, const float* __restrict__ W,
    const float* __restrict__ bias)
{
    __shared__ float4 xs4[Rrows][Hdim / 4];   // 32KB staged x tile
    __shared__ float  part[8][Rrows][32];     // 8KB per-slice partials
    __shared__ float  se[Rrows][32];

    const int tid  = threadIdx.x;
    const int lane = tid & 31;
    const int w    = tid >> 5;
    const int b0   = blockIdx.x * Rrows;

    // ---- Stage x: fully coalesced ------------------------------------------
    {
        const float4* xg = (const float4*)(x + (size_t)b0 * Hdim);
        float4* xf = (float4*)xs4;
        #pragma unroll
        for (int j = 0; j < 8; ++j)
            xf[tid + j * NTHR] = xg[tid + j * NTHR];
    }
    __syncthreads();

    // ---- Phase 1: packed-FMA GEMM partials ---------------------------------
    ull acc[Rrows];
    #pragma unroll
    for (int r = 0; r < Rrows; ++r) acc[r] = 0ull;

    const int  h0     = w * 128;
    const bool kvalid = (lane < N3K);

    #pragma unroll 2
    for (int hh = 0; hh < 128; hh += 4) {
        const int h  = h0 + hh;
        const int c4 = h >> 2;
        // W[h..h+3][lane], packed into two f32x2 operands
        float w0 = kvalid ? W[(size_t)(h + 0) * N3K + lane] : 0.f;
        float w1 = kvalid ? W[(size_t)(h + 1) * N3K + lane] : 0.f;
        float w2 = kvalid ? W[(size_t)(h + 2) * N3K + lane] : 0.f;
        float w3 = kvalid ? W[(size_t)(h + 3) * N3K + lane] : 0.f;
        ull wp01, wp23;
        asm("mov.b64 %0, {%1, %2};" : "=l"(wp01)
            : "r"(__float_as_uint(w0)), "r"(__float_as_uint(w1)));
        asm("mov.b64 %0, {%1, %2};" : "=l"(wp23)
            : "r"(__float_as_uint(w2)), "r"(__float_as_uint(w3)));
        #pragma unroll
        for (int r = 0; r < Rrows; ++r) {
            // one LDS.128: {x[h],x[h+1]} and {x[h+2],x[h+3]} already packed
            ulonglong2 xv = *(const ulonglong2*)&xs4[r][c4];
            FFMA2(acc[r], xv.x, wp01, acc[r]);
            FFMA2(acc[r], xv.y, wp23, acc[r]);
        }
    }
    #pragma unroll
    for (int r = 0; r < Rrows; ++r) {
        float lo = __uint_as_float((unsigned)(acc[r] & 0xFFFFFFFFull));
        float hi = __uint_as_float((unsigned)(acc[r] >> 32));
        part[w][r][lane] = lo + hi;
    }
    __syncthreads();

    // ---- Phase 2: reduce + bias + exp --------------------------------------
    if (tid < Rrows * N3K) {
        const int r = tid / N3K, k = tid - r * N3K;
        float s = 0.f;
        #pragma unroll
        for (int ww = 0; ww < 8; ++ww) s += part[ww][r][k];
        se[r][k] = expf(s + bias[k]);
    }
    __syncthreads();

    // ---- Phase 3: phi -> global --------------------------------------------
    #pragma unroll
    for (int i = 0; i < 2; ++i) {
        const int idx = tid + i * NTHR;        // 512 = 8 rows x 64 L
        const int r = idx >> 6, l = idx & 63;
        const float u = (float)l;
        float s = 0.f;
        #pragma unroll
        for (int k = 0; k < Kmix; ++k) {
            float d = se[r][20 + k] - u;
            s += se[r][k] * expf(-se[r][10 + k] * d * d);
        }
        g_phi[(size_t)(b0 + r) * Lw + l] = s;
    }
}

// ---------------------------------------------------------------------------
// Kernel B: out[b] = phi[b] @ chars[b].  4096 blocks x 160 threads,
// thread -> (v4 = tid%20 float4-column, g = tid/20 covering 8 L-slots).
// 8 float4 char loads prefetched up front -> high MLP, DRAM-bound (67% peak).
// ---------------------------------------------------------------------------
__global__ __launch_bounds__(160) void window_kernel(const float* __restrict__ chars,
                                                     float* __restrict__ out) {
    __shared__ float  phi_s[Lw];
    __shared__ float4 part[8][20];

    const int b   = blockIdx.x;
    const int tid = threadIdx.x;
    const int v4  = tid % 20;
    const int g   = tid / 20;

    const float4* ch = (const float4*)(chars + (size_t)b * Lw * Vv);
    float4 c[8];
    #pragma unroll
    for (int i = 0; i < 8; ++i)
        c[i] = ch[(g * 8 + i) * (Vv / 4) + v4];

    if (tid < Lw)
        phi_s[tid] = g_phi[(size_t)b * Lw + tid];
    __syncthreads();

    float4 acc = make_float4(0.f, 0.f, 0.f, 0.f);
    #pragma unroll
    for (int i = 0; i < 8; ++i) {
        float p = phi_s[g * 8 + i];
        acc.x += p * c[i].x;  acc.y += p * c[i].y;
        acc.z += p * c[i].z;  acc.w += p * c[i].w;
    }
    part[g][v4] = acc;
    __syncthreads();

    if (tid < 20) {
        float4 s = part[0][tid];
        #pragma unroll
        for (int g2 = 1; g2 < 8; ++g2) {
            float4 p = part[g2][tid];
            s.x += p.x;  s.y += p.y;  s.z += p.z;  s.w += p.w;
        }
        ((float4*)out)[(size_t)b * (Vv / 4) + tid] = s;
    }
}

// ---------------------------------------------------------------------------
extern "C" void kernel_launch(void* const* d_in, const int* in_sizes, int n_in,
                              void* d_out, int out_size) {
    const float* x     = (const float*)d_in[0];   // [4096, 1024]
    const float* chars = (const float*)d_in[1];   // [4096, 64, 80]
    const float* W     = (const float*)d_in[2];   // [1024, 30]
    const float* bvec  = (const float*)d_in[3];   // [30]
    float*       out   = (float*)d_out;           // [4096, 80]

    gemm_phi_kernel<<<NBLK, NTHR>>>(x, W, bvec);
    window_kernel<<<Bsz, 160>>>(chars, out);
}

// round 12
// speedup vs baseline: 1.8129x; 1.2842x over previous
#include <cuda_runtime.h>

#define Bsz 4096
#define Hdim 1024
#define Kmix 10
#define Lw 64
#define Vv 80
#define N3K 30
#define Rrows 16
#define NBLK (Bsz / Rrows)   // 256 blocks
#define NTHR 256

typedef unsigned long long ull;

// phi[b][l], written by kernel A, streamed by kernel B (1 MB)
__device__ float g_phi[Bsz * Lw];

// packed dual-FMA: d = a*b + c elementwise on {lo,hi} fp32 pairs
#define FFMA2(d, a, b, c) \
    asm("fma.rn.f32x2 %0, %1, %2, %3;" : "=l"(d) : "l"(a), "l"(b), "l"(c))

// Dynamic smem layout (82 KB total -> occ 2, single wave of 256 CTAs):
//   [0, 64K)        float4 xs4[16][256]    staged x rows
//   [64K, 80K)      float  part[8][16][32] per-slice GEMM partials
//   [80K, 82K)      float  se[16][32]      exp(alpha|beta|kappa)
#define SMEM_BYTES (64 * 1024 + 16 * 1024 + 2 * 1024)

// ---------------------------------------------------------------------------
// Kernel A: x@W + b -> exp -> mixture -> phi.
// 256 blocks x 256 threads, 16 batch rows/block (halves W L2 re-read vs 8).
// Warp w owns h-slice [w*128,(w+1)*128), lane = k. Staged x read as
// broadcast LDS.128 (packed {x[h],x[h+1]} pairs), fma.rn.f32x2 accumulates
// even/odd h. r in groups of 4 bounds register live-ranges (no spills at
// the 128-reg cap from __launch_bounds__(256,2)).
// ---------------------------------------------------------------------------
__global__ __launch_bounds__(NTHR, 2) void gemm_phi_kernel(
    const float* __restrict__ x, const float* __restrict__ W,
    const float* __restrict__ bias)
{
    extern __shared__ char dyn[];
    float4* xs4  = (float4*)dyn;                          // [16][256]
    float*  part = (float*)(dyn + 64 * 1024);             // [8][16][32]
    float*  se   = (float*)(dyn + 64 * 1024 + 16 * 1024); // [16][32]

    const int tid  = threadIdx.x;
    const int lane = tid & 31;
    const int w    = tid >> 5;
    const int b0   = blockIdx.x * Rrows;

    // ---- Stage x: fully coalesced (16 float4 per thread) -------------------
    {
        const float4* xg = (const float4*)(x + (size_t)b0 * Hdim);
        #pragma unroll
        for (int j = 0; j < 16; ++j)
            xs4[tid + j * NTHR] = xg[tid + j * NTHR];
    }
    __syncthreads();

    // ---- Phase 1: packed-FMA GEMM partials ---------------------------------
    ull acc[Rrows];
    #pragma unroll
    for (int r = 0; r < Rrows; ++r) acc[r] = 0ull;

    const int  h0     = w * 128;
    const bool kvalid = (lane < N3K);

    #pragma unroll 2
    for (int hh = 0; hh < 128; hh += 4) {
        const int h  = h0 + hh;
        const int c4 = h >> 2;
        float w0 = kvalid ? W[(size_t)(h + 0) * N3K + lane] : 0.f;
        float w1 = kvalid ? W[(size_t)(h + 1) * N3K + lane] : 0.f;
        float w2 = kvalid ? W[(size_t)(h + 2) * N3K + lane] : 0.f;
        float w3 = kvalid ? W[(size_t)(h + 3) * N3K + lane] : 0.f;
        ull wp01, wp23;
        asm("mov.b64 %0, {%1, %2};" : "=l"(wp01)
            : "r"(__float_as_uint(w0)), "r"(__float_as_uint(w1)));
        asm("mov.b64 %0, {%1, %2};" : "=l"(wp23)
            : "r"(__float_as_uint(w2)), "r"(__float_as_uint(w3)));
        #pragma unroll
        for (int rg = 0; rg < Rrows / 4; ++rg) {
            ulonglong2 xv[4];
            #pragma unroll
            for (int i = 0; i < 4; ++i)
                xv[i] = *(const ulonglong2*)&xs4[(rg * 4 + i) * (Hdim / 4) + c4];
            #pragma unroll
            for (int i = 0; i < 4; ++i) {
                FFMA2(acc[rg * 4 + i], xv[i].x, wp01, acc[rg * 4 + i]);
                FFMA2(acc[rg * 4 + i], xv[i].y, wp23, acc[rg * 4 + i]);
            }
        }
    }
    #pragma unroll
    for (int r = 0; r < Rrows; ++r) {
        float lo = __uint_as_float((unsigned)(acc[r] & 0xFFFFFFFFull));
        float hi = __uint_as_float((unsigned)(acc[r] >> 32));
        part[(w * Rrows + r) * 32 + lane] = lo + hi;
    }
    __syncthreads();

    // ---- Phase 2: reduce + bias + exp (480 items, 256 threads -> loop) -----
    for (int idx = tid; idx < Rrows * N3K; idx += NTHR) {
        const int r = idx / N3K, k = idx - r * N3K;
        float s = 0.f;
        #pragma unroll
        for (int ww = 0; ww < 8; ++ww) s += part[(ww * Rrows + r) * 32 + k];
        se[r * 32 + k] = expf(s + bias[k]);
    }
    __syncthreads();

    // ---- Phase 3: phi -> global --------------------------------------------
    #pragma unroll
    for (int i = 0; i < 4; ++i) {
        const int idx = tid + i * NTHR;        // 1024 = 16 rows x 64 L
        const int r = idx >> 6, l = idx & 63;
        const float u = (float)l;
        float s = 0.f;
        #pragma unroll
        for (int k = 0; k < Kmix; ++k) {
            float d = se[r * 32 + 20 + k] - u;
            s += se[r * 32 + k] * expf(-se[r * 32 + 10 + k] * d * d);
        }
        g_phi[(size_t)(b0 + r) * Lw + l] = s;
    }
}

// ---------------------------------------------------------------------------
// Kernel B: out[b] = phi[b] @ chars[b].  4096 blocks x 160 threads,
// thread -> (v4 = tid%20 float4-column, g = tid/20 covering 8 L-slots).
// 8 float4 char loads prefetched up front -> high MLP, DRAM-bound (67% peak).
// ---------------------------------------------------------------------------
__global__ __launch_bounds__(160) void window_kernel(const float* __restrict__ chars,
                                                     float* __restrict__ out) {
    __shared__ float  phi_s[Lw];
    __shared__ float4 part[8][20];

    const int b   = blockIdx.x;
    const int tid = threadIdx.x;
    const int v4  = tid % 20;
    const int g   = tid / 20;

    const float4* ch = (const float4*)(chars + (size_t)b * Lw * Vv);
    float4 c[8];
    #pragma unroll
    for (int i = 0; i < 8; ++i)
        c[i] = ch[(g * 8 + i) * (Vv / 4) + v4];

    if (tid < Lw)
        phi_s[tid] = g_phi[(size_t)b * Lw + tid];
    __syncthreads();

    float4 acc = make_float4(0.f, 0.f, 0.f, 0.f);
    #pragma unroll
    for (int i = 0; i < 8; ++i) {
        float p = phi_s[g * 8 + i];
        acc.x += p * c[i].x;  acc.y += p * c[i].y;
        acc.z += p * c[i].z;  acc.w += p * c[i].w;
    }
    part[g][v4] = acc;
    __syncthreads();

    if (tid < 20) {
        float4 s = part[0][tid];
        #pragma unroll
        for (int g2 = 1; g2 < 8; ++g2) {
            float4 p = part[g2][tid];
            s.x += p.x;  s.y += p.y;  s.z += p.z;  s.w += p.w;
        }
        ((float4*)out)[(size_t)b * (Vv / 4) + tid] = s;
    }
}

// ---------------------------------------------------------------------------
extern "C" void kernel_launch(void* const* d_in, const int* in_sizes, int n_in,
                              void* d_out, int out_size) {
    const float* x     = (const float*)d_in[0];   // [4096, 1024]
    const float* chars = (const float*)d_in[1];   // [4096, 64, 80]
    const float* W     = (const float*)d_in[2];   // [1024, 30]
    const float* bvec  = (const float*)d_in[3];   // [30]
    float*       out   = (float*)d_out;           // [4096, 80]

    cudaFuncSetAttribute(gemm_phi_kernel,
                         cudaFuncAttributeMaxDynamicSharedMemorySize, SMEM_BYTES);
    gemm_phi_kernel<<<NBLK, NTHR, SMEM_BYTES>>>(x, W, bvec);
    window_kernel<<<Bsz, 160>>>(chars, out);
}